// round 13
// baseline (speedup 1.0000x reference)
#include <cuda_runtime.h>
#include <cstdint>
#include <math.h>

#define BSZ   2
#define TSEQ  2048
#define DMOD  1024
#define NH    16
#define HDIM  64
#define MTOK  (BSZ*TSEQ)      /* 4096 */
#define NQT   (TSEQ/64)       /* 32 q-tiles */

// Scratch (device globals — no allocations allowed)
__device__ float g_q[(size_t)BSZ*NH*TSEQ*HDIM];   // [B,H,T,64] (Q pre-scaled by 1/8, tf32)
__device__ float g_k[(size_t)BSZ*NH*TSEQ*HDIM];   // [B,H,T,64] (tf32)
__device__ float g_vT[(size_t)BSZ*NH*HDIM*TSEQ];  // [B,H,64,T] (tf32, t-major!)
__device__ float g_att[(size_t)MTOK*DMOD];        // [B,T,D] (tf32-rounded)
__device__ float g_xr[(size_t)MTOK*DMOD];         // x, tf32-rounded
__device__ float g_wkqvT[(size_t)3*DMOD*DMOD];    // W_kqv^T  [3072,1024] (tf32)
__device__ float g_wprojT[(size_t)DMOD*DMOD];     // W_proj^T [1024,1024] (tf32)

extern __shared__ float dynsm[];

// ===========================================================================
// Helpers
// ===========================================================================
__device__ __forceinline__ uint32_t smem_u32(const void* p) {
    uint32_t a;
    asm("{ .reg .u64 t; cvta.to.shared.u64 t, %1; cvt.u32.u64 %0, t; }"
        : "=r"(a) : "l"(p));
    return a;
}
__device__ __forceinline__ float tf32r(float x) {
    uint32_t u;
    asm("cvt.rna.tf32.f32 %0, %1;" : "=r"(u) : "f"(x));
    return __uint_as_float(u);
}
__device__ __forceinline__ uint32_t tf32b(float x) {
    uint32_t u;
    asm("cvt.rna.tf32.f32 %0, %1;" : "=r"(u) : "f"(x));
    return u;
}
__device__ __forceinline__ void cp_async16(uint32_t sdst, const void* gsrc) {
    asm volatile("cp.async.cg.shared.global [%0], [%1], 16;" :: "r"(sdst), "l"(gsrc));
}
#define CP_COMMIT() asm volatile("cp.async.commit_group;" ::: "memory")
#define CP_WAIT(n)  asm volatile("cp.async.wait_group %0;" :: "n"(n) : "memory")
__device__ __forceinline__ void ldsm_x4(uint32_t* r, uint32_t addr) {
    asm volatile("ldmatrix.sync.aligned.m8n8.x4.b16 {%0,%1,%2,%3}, [%4];"
                 : "=r"(r[0]), "=r"(r[1]), "=r"(r[2]), "=r"(r[3]) : "r"(addr));
}
__device__ __forceinline__ void mma_tf32(float* c, const uint32_t* a, const uint32_t* b) {
    asm volatile("mma.sync.aligned.m16n8k8.row.col.f32.tf32.tf32.f32 "
                 "{%0,%1,%2,%3}, {%4,%5,%6,%7}, {%8,%9}, {%0,%1,%2,%3};"
                 : "+f"(c[0]), "+f"(c[1]), "+f"(c[2]), "+f"(c[3])
                 : "r"(a[0]), "r"(a[1]), "r"(a[2]), "r"(a[3]), "r"(b[0]), "r"(b[1]));
}

// ===========================================================================
// Fused pre-pass: tf32-round x; transpose+round both weight matrices.
// Flattened grid: [0,4096) round_x, [4096,7168) W_kqv^T, [7168,8192) W_proj^T.
// ===========================================================================
__global__ __launch_bounds__(256) void prep_k(const float* __restrict__ x,
                                              const float* __restrict__ Wkqv,
                                              const float* __restrict__ Wproj) {
    __shared__ float t[32][33];
    const int bx = blockIdx.x;
    if (bx < 4096) {
        int i = (bx * 256 + threadIdx.x) * 4;
        float4 v = *(const float4*)&x[i];
        v.x = tf32r(v.x); v.y = tf32r(v.y); v.z = tf32r(v.z); v.w = tf32r(v.w);
        *(float4*)&g_xr[i] = v;
        return;
    }
    const float* S;
    float* D;
    int gx, gy, R, C;
    if (bx < 4096 + 3072) {
        int b2 = bx - 4096;
        S = Wkqv; D = g_wkqvT; R = DMOD; C = 3*DMOD;
        gx = b2 % 96; gy = b2 / 96;
    } else {
        int b3 = bx - (4096 + 3072);
        S = Wproj; D = g_wprojT; R = DMOD; C = DMOD;
        gx = b3 % 32; gy = b3 / 32;
    }
    const int txx = threadIdx.x & 31;
    const int tyy = threadIdx.x >> 5;
    const int xx  = gx * 32 + txx;
    const int y0  = gy * 32;
    #pragma unroll
    for (int i = tyy; i < 32; i += 8)
        t[i][txx] = S[(size_t)(y0 + i) * C + xx];
    __syncthreads();
    const int xo  = y0 + txx;
    const int yo0 = gx * 32;
    #pragma unroll
    for (int i = tyy; i < 32; i += 8)
        D[(size_t)(yo0 + i) * R + xo] = tf32r(t[txx][i]);
}

// ===========================================================================
// tf32 mma.sync GEMM body — EXACT R5/R9 proven structure. DO NOT TOUCH.
// CTA 128x128, 8 warps (2m x 4n), warp tile 64x32, KC=16, 2-stage, static smem.
// ===========================================================================
#define KC 16
#define SSTR 20

__device__ __forceinline__ void gemm_load_stage(const float* __restrict__ A,
                                                const float* __restrict__ BT,
                                                float* As, float* Bs,
                                                int m0, int n0, int K, int k0) {
    const int tid = threadIdx.x;
    #pragma unroll
    for (int r = 0; r < 2; r++) {
        int idx = tid + r * 256;
        int row = idx >> 2, c4 = idx & 3;
        cp_async16(smem_u32(&As[row * SSTR + c4 * 4]),
                   &A[(size_t)(m0 + row) * K + k0 + c4 * 4]);
        cp_async16(smem_u32(&Bs[row * SSTR + c4 * 4]),
                   &BT[(size_t)(n0 + row) * K + k0 + c4 * 4]);
    }
    CP_COMMIT();
}

__device__ __forceinline__ void gemm_compute_stage(const float* As, const float* Bs,
                                                   int wm, int wn, int lane,
                                                   float c[4][4][4]) {
    #pragma unroll
    for (int oct = 0; oct < 2; oct++) {
        const int k0 = oct * 8;
        uint32_t a[4][4];
        #pragma unroll
        for (int am = 0; am < 4; am++) {
            int row = wm + am * 16 + ((lane >> 3) & 1) * 8 + (lane & 7);
            int col = k0 + (lane >> 4) * 4;
            ldsm_x4(a[am], smem_u32(&As[row * SSTR + col]));
        }
        uint32_t b[4][2];
        #pragma unroll
        for (int p = 0; p < 2; p++) {
            int row = wn + p * 16 + ((lane >> 4) & 1) * 8 + (lane & 7);
            int col = k0 + ((lane >> 3) & 1) * 4;
            uint32_t r[4];
            ldsm_x4(r, smem_u32(&Bs[row * SSTR + col]));
            b[2*p    ][0] = r[0]; b[2*p    ][1] = r[1];
            b[2*p + 1][0] = r[2]; b[2*p + 1][1] = r[3];
        }
        #pragma unroll
        for (int am = 0; am < 4; am++)
            #pragma unroll
            for (int an = 0; an < 4; an++)
                mma_tf32(c[am][an], a[am], b[an]);
    }
}

__device__ __forceinline__ void gemm_mma_body(const float* __restrict__ A,
                                              const float* __restrict__ BT,
                                              int m0, int n0, int K,
                                              float c[4][4][4]) {
    __shared__ __align__(16) float As[2][128 * SSTR];
    __shared__ __align__(16) float Bs[2][128 * SSTR];
    const int lane = threadIdx.x & 31;
    const int wid  = threadIdx.x >> 5;
    const int wm = (wid & 1) * 64;
    const int wn = (wid >> 1) * 32;

    gemm_load_stage(A, BT, As[0], Bs[0], m0, n0, K, 0);
    const int nk = K / KC;
    for (int kt = 0; kt < nk; kt++) {
        if (kt + 1 < nk) {
            gemm_load_stage(A, BT, As[(kt+1)&1], Bs[(kt+1)&1], m0, n0, K, (kt+1)*KC);
            CP_WAIT(1);
        } else {
            CP_WAIT(0);
        }
        __syncthreads();
        gemm_compute_stage(As[kt&1], Bs[kt&1], wm, wn, lane, c);
        __syncthreads();
    }
}

// QKV GEMM epilogue: q/k -> [B,H,T,64] tf32 (q pre-scaled 1/8); v -> g_vT [B,H,64,T].
__global__ __launch_bounds__(256) void gemm_qkv_mma(const float* __restrict__ bias) {
    float c[4][4][4] = {};
    const int m0 = blockIdx.y * 128, n0 = blockIdx.x * 128;
    gemm_mma_body(g_xr, g_wkqvT, m0, n0, DMOD, c);
    const int lane = threadIdx.x & 31;
    const int wid  = threadIdx.x >> 5;
    const int wm = (wid & 1) * 64, wn = (wid >> 1) * 32;
    #pragma unroll
    for (int an = 0; an < 4; an++) {
        int cb = n0 + wn + an * 8 + (lane & 3) * 2;
        int which = cb >> 10;
        int h  = (cb >> 6) & (NH - 1);
        int ch = cb & 63;
        float2 bb = *(const float2*)&bias[cb];
        #pragma unroll
        for (int am = 0; am < 4; am++) {
            #pragma unroll
            for (int hf = 0; hf < 2; hf++) {
                int m = m0 + wm + am * 16 + (lane >> 2) + hf * 8;
                int b = m >> 11, t = m & (TSEQ - 1);
                float vx = c[am][an][2*hf + 0] + bb.x;
                float vy = c[am][an][2*hf + 1] + bb.y;
                if (which == 2) {
                    size_t vb = (size_t)(b * NH + h) * HDIM;
                    g_vT[(vb + ch    ) * TSEQ + t] = tf32r(vx);
                    g_vT[(vb + ch + 1) * TSEQ + t] = tf32r(vy);
                } else {
                    float* dst = (which == 0) ? g_q : g_k;
                    float qs = (which == 0) ? 0.125f : 1.0f;
                    float2 v;
                    v.x = tf32r(vx * qs);
                    v.y = tf32r(vy * qs);
                    *(float2*)&dst[((size_t)(b * NH + h) * TSEQ + t) * HDIM + ch] = v;
                }
            }
        }
    }
}

// Output projection: out = g_att @ WprojT^T + b
__global__ __launch_bounds__(256) void gemm_proj_mma(const float* __restrict__ bias,
                                                     float* __restrict__ C) {
    float c[4][4][4] = {};
    const int m0 = blockIdx.y * 128, n0 = blockIdx.x * 128;
    gemm_mma_body(g_att, g_wprojT, m0, n0, DMOD, c);
    const int lane = threadIdx.x & 31;
    const int wid  = threadIdx.x >> 5;
    const int wm = (wid & 1) * 64, wn = (wid >> 1) * 32;
    #pragma unroll
    for (int an = 0; an < 4; an++) {
        int cb = n0 + wn + an * 8 + (lane & 3) * 2;
        float2 bb = *(const float2*)&bias[cb];
        #pragma unroll
        for (int am = 0; am < 4; am++) {
            #pragma unroll
            for (int hf = 0; hf < 2; hf++) {
                int m = m0 + wm + am * 16 + (lane >> 2) + hf * 8;
                float2 v;
                v.x = c[am][an][2*hf + 0] + bb.x;
                v.y = c[am][an][2*hf + 1] + bb.y;
                *(float2*)&C[(size_t)m * DMOD + cb] = v;
            }
        }
    }
}

// ===========================================================================
// mma.sync flash attention — EXACT R9/R11 body. ONLY change this round:
// __launch_bounds__(128, 3) -> cap 170 regs, 3 CTAs/SM (smem 3x69632=204KB
// fits 228KB) -> 3 warps/SMSP so softmax bubbles are filled by other warps'
// tensor work.
// ===========================================================================
#define ATSTR 68
#define ATILE (64 * ATSTR)
#define ATT_SMEM (4 * ATILE * 4)

__device__ __forceinline__ void attn_prefetch(const float* __restrict__ Kb,
                                              const float* __restrict__ VTb,
                                              float* Kd, float* Vd, int kt) {
    const int tid = threadIdx.x;
    #pragma unroll
    for (int r = 0; r < 8; r++) {
        int f = tid + r * 128;
        int row = f >> 4, c4 = f & 15;
        cp_async16(smem_u32(&Kd[row * ATSTR + c4 * 4]),
                   Kb + ((size_t)kt * 64 + row) * HDIM + c4 * 4);
        cp_async16(smem_u32(&Vd[row * ATSTR + c4 * 4]),
                   VTb + (size_t)row * TSEQ + kt * 64 + c4 * 4);
    }
    CP_COMMIT();
}

__device__ void attn_pass(int qt, int bh, float* Kbuf, float* Vbuf) {
    const int tid = threadIdx.x;
    const int lane = tid & 31;
    const int w    = tid >> 5;

    const float* Qb  = g_q  + ((size_t)bh * TSEQ + (size_t)qt * 64) * HDIM;
    const float* Kb  = g_k  + (size_t)bh * TSEQ * HDIM;
    const float* VTb = g_vT + (size_t)bh * HDIM * TSEQ;

    __syncthreads();   // prior pass fully done with smem
    // Stage Q through Kbuf[1], load A-fragments to registers
    {
        const float4* Qt = (const float4*)Qb;
        float* Qs = Kbuf + ATILE;
        #pragma unroll
        for (int r = 0; r < 8; r++) {
            int f = tid + r * 128;
            int row = f >> 4, c4 = f & 15;
            *(float4*)&Qs[row * ATSTR + c4 * 4] = Qt[f];
        }
    }
    __syncthreads();
    uint32_t qf[8][4];
    {
        const float* Qs = Kbuf + ATILE;
        int row = w * 16 + ((lane >> 3) & 1) * 8 + (lane & 7);
        #pragma unroll
        for (int oct = 0; oct < 8; oct++)
            ldsm_x4(qf[oct], smem_u32(&Qs[row * ATSTR + oct * 8 + (lane >> 4) * 4]));
    }

    // Prefetch k-tile 0 into buffer 0 (doesn't touch Kbuf[1] holding Q)
    attn_prefetch(Kb, VTb, Kbuf, Vbuf, 0);

    float mst[2] = {-1e30f, -1e30f}, lst[2] = {0.f, 0.f};
    float o[8][4];
    #pragma unroll
    for (int an = 0; an < 8; an++)
        #pragma unroll
        for (int e = 0; e < 4; e++) o[an][e] = 0.f;

    const int t3   = lane & 3;
    const int src0 = (lane & ~3) | (t3 >> 1);
    const int src2 = src0 + 2;

    for (int kt = 0; kt <= qt; kt++) {
        CP_WAIT(0);
        __syncthreads();   // stage kt visible; all warps done with buf[(kt+1)&1]
        if (kt + 1 <= qt)
            attn_prefetch(Kb, VTb, Kbuf + ((kt+1)&1)*ATILE, Vbuf + ((kt+1)&1)*ATILE, kt+1);

        const float* Ks  = Kbuf + (kt & 1) * ATILE;
        const float* Vts = Vbuf + (kt & 1) * ATILE;

        // --- S = Q K^T (warp: 16q x 64k)
        float c[8][4];
        #pragma unroll
        for (int an = 0; an < 8; an++)
            #pragma unroll
            for (int e = 0; e < 4; e++) c[an][e] = 0.f;
        #pragma unroll
        for (int oct = 0; oct < 8; oct++) {
            uint32_t b[8][2];
            #pragma unroll
            for (int p = 0; p < 4; p++) {
                int row = p * 16 + ((lane >> 4) & 1) * 8 + (lane & 7);
                int col = oct * 8 + ((lane >> 3) & 1) * 4;
                uint32_t t4[4];
                ldsm_x4(t4, smem_u32(&Ks[row * ATSTR + col]));
                b[2*p    ][0] = t4[0]; b[2*p    ][1] = t4[1];
                b[2*p + 1][0] = t4[2]; b[2*p + 1][1] = t4[3];
            }
            #pragma unroll
            for (int an = 0; an < 8; an++) mma_tf32(c[an], qf[oct], b[an]);
        }

        // --- causal mask (diagonal tile only)
        if (kt == qt) {
            int r0 = w * 16 + (lane >> 2);
            #pragma unroll
            for (int an = 0; an < 8; an++) {
                int k0 = an * 8 + t3 * 2;
                if (k0     > r0)     c[an][0] = -1e30f;
                if (k0 + 1 > r0)     c[an][1] = -1e30f;
                if (k0     > r0 + 8) c[an][2] = -1e30f;
                if (k0 + 1 > r0 + 8) c[an][3] = -1e30f;
            }
        }

        // --- online softmax
        #pragma unroll
        for (int h = 0; h < 2; h++) {
            float mt = -1e30f;
            #pragma unroll
            for (int an = 0; an < 8; an++)
                mt = fmaxf(mt, fmaxf(c[an][2*h], c[an][2*h + 1]));
            mt = fmaxf(mt, __shfl_xor_sync(0xffffffffu, mt, 1));
            mt = fmaxf(mt, __shfl_xor_sync(0xffffffffu, mt, 2));
            float mnew = fmaxf(mst[h], mt);
            float corr = __expf(mst[h] - mnew);
            float sum = 0.f;
            #pragma unroll
            for (int an = 0; an < 8; an++) {
                c[an][2*h]     = __expf(c[an][2*h]     - mnew);
                c[an][2*h + 1] = __expf(c[an][2*h + 1] - mnew);
                sum += c[an][2*h] + c[an][2*h + 1];
            }
            sum += __shfl_xor_sync(0xffffffffu, sum, 1);
            sum += __shfl_xor_sync(0xffffffffu, sum, 2);
            lst[h] = lst[h] * corr + sum;
            mst[h] = mnew;
            #pragma unroll
            for (int an = 0; an < 8; an++) {
                o[an][2*h]     *= corr;
                o[an][2*h + 1] *= corr;
            }
        }

        // --- O += P V: P A-fragments built by in-register lane permute.
        #pragma unroll
        for (int ko = 0; ko < 8; ko++) {
            float v00 = __shfl_sync(0xffffffffu, c[ko][0], src0);
            float v01 = __shfl_sync(0xffffffffu, c[ko][1], src0);
            float v10 = __shfl_sync(0xffffffffu, c[ko][2], src0);
            float v11 = __shfl_sync(0xffffffffu, c[ko][3], src0);
            float w00 = __shfl_sync(0xffffffffu, c[ko][0], src2);
            float w01 = __shfl_sync(0xffffffffu, c[ko][1], src2);
            float w10 = __shfl_sync(0xffffffffu, c[ko][2], src2);
            float w11 = __shfl_sync(0xffffffffu, c[ko][3], src2);
            uint32_t pf[4];
            pf[0] = tf32b((t3 & 1) ? v01 : v00);
            pf[1] = tf32b((t3 & 1) ? v11 : v10);
            pf[2] = tf32b((t3 & 1) ? w01 : w00);
            pf[3] = tf32b((t3 & 1) ? w11 : w10);

            uint32_t b[8][2];
            #pragma unroll
            for (int p = 0; p < 4; p++) {
                int row = p * 16 + ((lane >> 4) & 1) * 8 + (lane & 7);
                int col = ko * 8 + ((lane >> 3) & 1) * 4;
                uint32_t t4[4];
                ldsm_x4(t4, smem_u32(&Vts[row * ATSTR + col]));
                b[2*p    ][0] = t4[0]; b[2*p    ][1] = t4[1];
                b[2*p + 1][0] = t4[2]; b[2*p + 1][1] = t4[3];
            }
            #pragma unroll
            for (int an = 0; an < 8; an++) mma_tf32(o[an], pf, b[an]);
        }
    }

    // --- epilogue: normalize, tf32-round, write [B,T,D]
    const int b  = bh >> 4;
    const int hd = bh & 15;
    const int r0 = w * 16 + (lane >> 2);
    #pragma unroll
    for (int h = 0; h < 2; h++) {
        float inv = 1.0f / lst[h];
        int t = qt * 64 + r0 + h * 8;
        float* orow = &g_att[((size_t)b * TSEQ + t) * DMOD + hd * HDIM];
        #pragma unroll
        for (int an = 0; an < 8; an++) {
            int d = an * 8 + t3 * 2;
            float2 v;
            v.x = tf32r(o[an][2*h]     * inv);
            v.y = tf32r(o[an][2*h + 1] * inv);
            *(float2*)&orow[d] = v;
        }
    }
}

__global__ __launch_bounds__(128, 3) void attn_mma() {
    float* Kbuf = dynsm;               // [2][ATILE]
    float* Vbuf = dynsm + 2 * ATILE;   // [2][ATILE]
    const int bh = blockIdx.y;
    attn_pass(NQT - 1 - blockIdx.x, bh, Kbuf, Vbuf);   // long pass first
    attn_pass(blockIdx.x,           bh, Kbuf, Vbuf);   // short pass second
}

// ---------------------------------------------------------------------------
extern "C" void kernel_launch(void* const* d_in, const int* in_sizes, int n_in,
                              void* d_out, int out_size) {
    (void)in_sizes; (void)n_in; (void)out_size;
    const float* x     = (const float*)d_in[0];
    const float* Wkqv  = (const float*)d_in[1];
    const float* bkqv  = (const float*)d_in[2];
    const float* Wproj = (const float*)d_in[3];
    const float* bproj = (const float*)d_in[4];
    float* out = (float*)d_out;

    cudaFuncSetAttribute(attn_mma, cudaFuncAttributeMaxDynamicSharedMemorySize, ATT_SMEM);

    prep_k<<<4096 + 3072 + 1024, 256>>>(x, Wkqv, Wproj);

    gemm_qkv_mma <<<dim3(3*DMOD/128, MTOK/128), 256>>>(bkqv);
    attn_mma     <<<dim3(NQT/2, BSZ*NH),        128, ATT_SMEM>>>();
    gemm_proj_mma<<<dim3(DMOD/128,  MTOK/128),  256>>>(bproj, out);
}

// round 14
// speedup vs baseline: 1.0184x; 1.0184x over previous
#include <cuda_runtime.h>
#include <cstdint>
#include <math.h>

#define BSZ   2
#define TSEQ  2048
#define DMOD  1024
#define NH    16
#define HDIM  64
#define MTOK  (BSZ*TSEQ)      /* 4096 */
#define NQT   (TSEQ/64)       /* 32 q-tiles */

// Scratch (device globals — no allocations allowed)
__device__ float g_q[(size_t)BSZ*NH*TSEQ*HDIM];   // [B,H,T,64] (Q scaled by log2e/8, tf32)
__device__ float g_k[(size_t)BSZ*NH*TSEQ*HDIM];   // [B,H,T,64] (tf32)
__device__ float g_vT[(size_t)BSZ*NH*HDIM*TSEQ];  // [B,H,64,T] (tf32, t-major!)
__device__ float g_att[(size_t)MTOK*DMOD];        // [B,T,D] (tf32-rounded)
__device__ float g_xr[(size_t)MTOK*DMOD];         // x, tf32-rounded
__device__ float g_wkqvT[(size_t)3*DMOD*DMOD];    // W_kqv^T  [3072,1024] (tf32)
__device__ float g_wprojT[(size_t)DMOD*DMOD];     // W_proj^T [1024,1024] (tf32)

extern __shared__ float dynsm[];

// ===========================================================================
// Helpers
// ===========================================================================
__device__ __forceinline__ uint32_t smem_u32(const void* p) {
    uint32_t a;
    asm("{ .reg .u64 t; cvta.to.shared.u64 t, %1; cvt.u32.u64 %0, t; }"
        : "=r"(a) : "l"(p));
    return a;
}
__device__ __forceinline__ float tf32r(float x) {
    uint32_t u;
    asm("cvt.rna.tf32.f32 %0, %1;" : "=r"(u) : "f"(x));
    return __uint_as_float(u);
}
__device__ __forceinline__ uint32_t tf32b(float x) {
    uint32_t u;
    asm("cvt.rna.tf32.f32 %0, %1;" : "=r"(u) : "f"(x));
    return u;
}
__device__ __forceinline__ void cp_async16(uint32_t sdst, const void* gsrc) {
    asm volatile("cp.async.cg.shared.global [%0], [%1], 16;" :: "r"(sdst), "l"(gsrc));
}
#define CP_COMMIT() asm volatile("cp.async.commit_group;" ::: "memory")
#define CP_WAIT(n)  asm volatile("cp.async.wait_group %0;" :: "n"(n) : "memory")
__device__ __forceinline__ void ldsm_x4(uint32_t* r, uint32_t addr) {
    asm volatile("ldmatrix.sync.aligned.m8n8.x4.b16 {%0,%1,%2,%3}, [%4];"
                 : "=r"(r[0]), "=r"(r[1]), "=r"(r[2]), "=r"(r[3]) : "r"(addr));
}
__device__ __forceinline__ void mma_tf32(float* c, const uint32_t* a, const uint32_t* b) {
    asm volatile("mma.sync.aligned.m16n8k8.row.col.f32.tf32.tf32.f32 "
                 "{%0,%1,%2,%3}, {%4,%5,%6,%7}, {%8,%9}, {%0,%1,%2,%3};"
                 : "+f"(c[0]), "+f"(c[1]), "+f"(c[2]), "+f"(c[3])
                 : "r"(a[0]), "r"(a[1]), "r"(a[2]), "r"(a[3]), "r"(b[0]), "r"(b[1]));
}
// Bare hardware exp2 (no argument FMUL — scores are pre-scaled by log2e).
__device__ __forceinline__ float ex2(float x) {
    float r;
    asm("ex2.approx.f32 %0, %1;" : "=f"(r) : "f"(x));
    return r;
}

// ===========================================================================
// Fused pre-pass: tf32-round x; transpose+round both weight matrices.
// Flattened grid: [0,4096) round_x, [4096,7168) W_kqv^T, [7168,8192) W_proj^T.
// ===========================================================================
__global__ __launch_bounds__(256) void prep_k(const float* __restrict__ x,
                                              const float* __restrict__ Wkqv,
                                              const float* __restrict__ Wproj) {
    __shared__ float t[32][33];
    const int bx = blockIdx.x;
    if (bx < 4096) {
        int i = (bx * 256 + threadIdx.x) * 4;
        float4 v = *(const float4*)&x[i];
        v.x = tf32r(v.x); v.y = tf32r(v.y); v.z = tf32r(v.z); v.w = tf32r(v.w);
        *(float4*)&g_xr[i] = v;
        return;
    }
    const float* S;
    float* D;
    int gx, gy, R, C;
    if (bx < 4096 + 3072) {
        int b2 = bx - 4096;
        S = Wkqv; D = g_wkqvT; R = DMOD; C = 3*DMOD;
        gx = b2 % 96; gy = b2 / 96;
    } else {
        int b3 = bx - (4096 + 3072);
        S = Wproj; D = g_wprojT; R = DMOD; C = DMOD;
        gx = b3 % 32; gy = b3 / 32;
    }
    const int txx = threadIdx.x & 31;
    const int tyy = threadIdx.x >> 5;
    const int xx  = gx * 32 + txx;
    const int y0  = gy * 32;
    #pragma unroll
    for (int i = tyy; i < 32; i += 8)
        t[i][txx] = S[(size_t)(y0 + i) * C + xx];
    __syncthreads();
    const int xo  = y0 + txx;
    const int yo0 = gx * 32;
    #pragma unroll
    for (int i = tyy; i < 32; i += 8)
        D[(size_t)(yo0 + i) * R + xo] = tf32r(t[txx][i]);
}

// ===========================================================================
// tf32 mma.sync GEMM body — EXACT R5/R9 proven structure. DO NOT TOUCH.
// CTA 128x128, 8 warps (2m x 4n), warp tile 64x32, KC=16, 2-stage, static smem.
// ===========================================================================
#define KC 16
#define SSTR 20

__device__ __forceinline__ void gemm_load_stage(const float* __restrict__ A,
                                                const float* __restrict__ BT,
                                                float* As, float* Bs,
                                                int m0, int n0, int K, int k0) {
    const int tid = threadIdx.x;
    #pragma unroll
    for (int r = 0; r < 2; r++) {
        int idx = tid + r * 256;
        int row = idx >> 2, c4 = idx & 3;
        cp_async16(smem_u32(&As[row * SSTR + c4 * 4]),
                   &A[(size_t)(m0 + row) * K + k0 + c4 * 4]);
        cp_async16(smem_u32(&Bs[row * SSTR + c4 * 4]),
                   &BT[(size_t)(n0 + row) * K + k0 + c4 * 4]);
    }
    CP_COMMIT();
}

__device__ __forceinline__ void gemm_compute_stage(const float* As, const float* Bs,
                                                   int wm, int wn, int lane,
                                                   float c[4][4][4]) {
    #pragma unroll
    for (int oct = 0; oct < 2; oct++) {
        const int k0 = oct * 8;
        uint32_t a[4][4];
        #pragma unroll
        for (int am = 0; am < 4; am++) {
            int row = wm + am * 16 + ((lane >> 3) & 1) * 8 + (lane & 7);
            int col = k0 + (lane >> 4) * 4;
            ldsm_x4(a[am], smem_u32(&As[row * SSTR + col]));
        }
        uint32_t b[4][2];
        #pragma unroll
        for (int p = 0; p < 2; p++) {
            int row = wn + p * 16 + ((lane >> 4) & 1) * 8 + (lane & 7);
            int col = k0 + ((lane >> 3) & 1) * 4;
            uint32_t r[4];
            ldsm_x4(r, smem_u32(&Bs[row * SSTR + col]));
            b[2*p    ][0] = r[0]; b[2*p    ][1] = r[1];
            b[2*p + 1][0] = r[2]; b[2*p + 1][1] = r[3];
        }
        #pragma unroll
        for (int am = 0; am < 4; am++)
            #pragma unroll
            for (int an = 0; an < 4; an++)
                mma_tf32(c[am][an], a[am], b[an]);
    }
}

__device__ __forceinline__ void gemm_mma_body(const float* __restrict__ A,
                                              const float* __restrict__ BT,
                                              int m0, int n0, int K,
                                              float c[4][4][4]) {
    __shared__ __align__(16) float As[2][128 * SSTR];
    __shared__ __align__(16) float Bs[2][128 * SSTR];
    const int lane = threadIdx.x & 31;
    const int wid  = threadIdx.x >> 5;
    const int wm = (wid & 1) * 64;
    const int wn = (wid >> 1) * 32;

    gemm_load_stage(A, BT, As[0], Bs[0], m0, n0, K, 0);
    const int nk = K / KC;
    for (int kt = 0; kt < nk; kt++) {
        if (kt + 1 < nk) {
            gemm_load_stage(A, BT, As[(kt+1)&1], Bs[(kt+1)&1], m0, n0, K, (kt+1)*KC);
            CP_WAIT(1);
        } else {
            CP_WAIT(0);
        }
        __syncthreads();
        gemm_compute_stage(As[kt&1], Bs[kt&1], wm, wn, lane, c);
        __syncthreads();
    }
}

// QKV GEMM epilogue: q/k -> [B,H,T,64] tf32; v -> g_vT [B,H,64,T].
// Q is scaled by log2(e)/8 so attention scores land in the exp2 domain.
#define QSCALE (0.125f * 1.44269504088896f)

__global__ __launch_bounds__(256) void gemm_qkv_mma(const float* __restrict__ bias) {
    float c[4][4][4] = {};
    const int m0 = blockIdx.y * 128, n0 = blockIdx.x * 128;
    gemm_mma_body(g_xr, g_wkqvT, m0, n0, DMOD, c);
    const int lane = threadIdx.x & 31;
    const int wid  = threadIdx.x >> 5;
    const int wm = (wid & 1) * 64, wn = (wid >> 1) * 32;
    #pragma unroll
    for (int an = 0; an < 4; an++) {
        int cb = n0 + wn + an * 8 + (lane & 3) * 2;
        int which = cb >> 10;
        int h  = (cb >> 6) & (NH - 1);
        int ch = cb & 63;
        float2 bb = *(const float2*)&bias[cb];
        #pragma unroll
        for (int am = 0; am < 4; am++) {
            #pragma unroll
            for (int hf = 0; hf < 2; hf++) {
                int m = m0 + wm + am * 16 + (lane >> 2) + hf * 8;
                int b = m >> 11, t = m & (TSEQ - 1);
                float vx = c[am][an][2*hf + 0] + bb.x;
                float vy = c[am][an][2*hf + 1] + bb.y;
                if (which == 2) {
                    size_t vb = (size_t)(b * NH + h) * HDIM;
                    g_vT[(vb + ch    ) * TSEQ + t] = tf32r(vx);
                    g_vT[(vb + ch + 1) * TSEQ + t] = tf32r(vy);
                } else {
                    float* dst = (which == 0) ? g_q : g_k;
                    float qs = (which == 0) ? QSCALE : 1.0f;
                    float2 v;
                    v.x = tf32r(vx * qs);
                    v.y = tf32r(vy * qs);
                    *(float2*)&dst[((size_t)(b * NH + h) * TSEQ + t) * HDIM + ch] = v;
                }
            }
        }
    }
}

// Output projection: out = g_att @ WprojT^T + b
__global__ __launch_bounds__(256) void gemm_proj_mma(const float* __restrict__ bias,
                                                     float* __restrict__ C) {
    float c[4][4][4] = {};
    const int m0 = blockIdx.y * 128, n0 = blockIdx.x * 128;
    gemm_mma_body(g_att, g_wprojT, m0, n0, DMOD, c);
    const int lane = threadIdx.x & 31;
    const int wid  = threadIdx.x >> 5;
    const int wm = (wid & 1) * 64, wn = (wid >> 1) * 32;
    #pragma unroll
    for (int an = 0; an < 4; an++) {
        int cb = n0 + wn + an * 8 + (lane & 3) * 2;
        float2 bb = *(const float2*)&bias[cb];
        #pragma unroll
        for (int am = 0; am < 4; am++) {
            #pragma unroll
            for (int hf = 0; hf < 2; hf++) {
                int m = m0 + wm + am * 16 + (lane >> 2) + hf * 8;
                float2 v;
                v.x = c[am][an][2*hf + 0] + bb.x;
                v.y = c[am][an][2*hf + 1] + bb.y;
                *(float2*)&C[(size_t)m * DMOD + cb] = v;
            }
        }
    }
}

// ===========================================================================
// mma.sync flash attention — R9/R11 body (2 CTAs/SM, no occupancy hint).
// Softmax in exp2 domain: scores are pre-scaled by log2e, so p = ex2(s - m)
// with bare MUFU.EX2 (no argument FMUL). exp2(-1e30) = 0 handles the mask.
// Balanced grid: each CTA runs qt=NQT-1-bx then qt=bx (33 tile-iterations).
// ===========================================================================
#define ATSTR 68
#define ATILE (64 * ATSTR)
#define ATT_SMEM (4 * ATILE * 4)

__device__ __forceinline__ void attn_prefetch(const float* __restrict__ Kb,
                                              const float* __restrict__ VTb,
                                              float* Kd, float* Vd, int kt) {
    const int tid = threadIdx.x;
    #pragma unroll
    for (int r = 0; r < 8; r++) {
        int f = tid + r * 128;
        int row = f >> 4, c4 = f & 15;
        cp_async16(smem_u32(&Kd[row * ATSTR + c4 * 4]),
                   Kb + ((size_t)kt * 64 + row) * HDIM + c4 * 4);
        cp_async16(smem_u32(&Vd[row * ATSTR + c4 * 4]),
                   VTb + (size_t)row * TSEQ + kt * 64 + c4 * 4);
    }
    CP_COMMIT();
}

__device__ void attn_pass(int qt, int bh, float* Kbuf, float* Vbuf) {
    const int tid = threadIdx.x;
    const int lane = tid & 31;
    const int w    = tid >> 5;

    const float* Qb  = g_q  + ((size_t)bh * TSEQ + (size_t)qt * 64) * HDIM;
    const float* Kb  = g_k  + (size_t)bh * TSEQ * HDIM;
    const float* VTb = g_vT + (size_t)bh * HDIM * TSEQ;

    __syncthreads();   // prior pass fully done with smem
    // Stage Q through Kbuf[1], load A-fragments to registers
    {
        const float4* Qt = (const float4*)Qb;
        float* Qs = Kbuf + ATILE;
        #pragma unroll
        for (int r = 0; r < 8; r++) {
            int f = tid + r * 128;
            int row = f >> 4, c4 = f & 15;
            *(float4*)&Qs[row * ATSTR + c4 * 4] = Qt[f];
        }
    }
    __syncthreads();
    uint32_t qf[8][4];
    {
        const float* Qs = Kbuf + ATILE;
        int row = w * 16 + ((lane >> 3) & 1) * 8 + (lane & 7);
        #pragma unroll
        for (int oct = 0; oct < 8; oct++)
            ldsm_x4(qf[oct], smem_u32(&Qs[row * ATSTR + oct * 8 + (lane >> 4) * 4]));
    }

    // Prefetch k-tile 0 into buffer 0 (doesn't touch Kbuf[1] holding Q)
    attn_prefetch(Kb, VTb, Kbuf, Vbuf, 0);

    float mst[2] = {-1e30f, -1e30f}, lst[2] = {0.f, 0.f};
    float o[8][4];
    #pragma unroll
    for (int an = 0; an < 8; an++)
        #pragma unroll
        for (int e = 0; e < 4; e++) o[an][e] = 0.f;

    const int t3   = lane & 3;
    const int src0 = (lane & ~3) | (t3 >> 1);
    const int src2 = src0 + 2;

    for (int kt = 0; kt <= qt; kt++) {
        CP_WAIT(0);
        __syncthreads();   // stage kt visible; all warps done with buf[(kt+1)&1]
        if (kt + 1 <= qt)
            attn_prefetch(Kb, VTb, Kbuf + ((kt+1)&1)*ATILE, Vbuf + ((kt+1)&1)*ATILE, kt+1);

        const float* Ks  = Kbuf + (kt & 1) * ATILE;
        const float* Vts = Vbuf + (kt & 1) * ATILE;

        // --- S = Q K^T (warp: 16q x 64k); scores already in log2 units
        float c[8][4];
        #pragma unroll
        for (int an = 0; an < 8; an++)
            #pragma unroll
            for (int e = 0; e < 4; e++) c[an][e] = 0.f;
        #pragma unroll
        for (int oct = 0; oct < 8; oct++) {
            uint32_t b[8][2];
            #pragma unroll
            for (int p = 0; p < 4; p++) {
                int row = p * 16 + ((lane >> 4) & 1) * 8 + (lane & 7);
                int col = oct * 8 + ((lane >> 3) & 1) * 4;
                uint32_t t4[4];
                ldsm_x4(t4, smem_u32(&Ks[row * ATSTR + col]));
                b[2*p    ][0] = t4[0]; b[2*p    ][1] = t4[1];
                b[2*p + 1][0] = t4[2]; b[2*p + 1][1] = t4[3];
            }
            #pragma unroll
            for (int an = 0; an < 8; an++) mma_tf32(c[an], qf[oct], b[an]);
        }

        // --- causal mask (diagonal tile only)
        if (kt == qt) {
            int r0 = w * 16 + (lane >> 2);
            #pragma unroll
            for (int an = 0; an < 8; an++) {
                int k0 = an * 8 + t3 * 2;
                if (k0     > r0)     c[an][0] = -1e30f;
                if (k0 + 1 > r0)     c[an][1] = -1e30f;
                if (k0     > r0 + 8) c[an][2] = -1e30f;
                if (k0 + 1 > r0 + 8) c[an][3] = -1e30f;
            }
        }

        // --- online softmax (exp2 domain: bare MUFU.EX2)
        #pragma unroll
        for (int h = 0; h < 2; h++) {
            float mt = -1e30f;
            #pragma unroll
            for (int an = 0; an < 8; an++)
                mt = fmaxf(mt, fmaxf(c[an][2*h], c[an][2*h + 1]));
            mt = fmaxf(mt, __shfl_xor_sync(0xffffffffu, mt, 1));
            mt = fmaxf(mt, __shfl_xor_sync(0xffffffffu, mt, 2));
            float mnew = fmaxf(mst[h], mt);
            float corr = ex2(mst[h] - mnew);
            float sum = 0.f;
            #pragma unroll
            for (int an = 0; an < 8; an++) {
                c[an][2*h]     = ex2(c[an][2*h]     - mnew);
                c[an][2*h + 1] = ex2(c[an][2*h + 1] - mnew);
                sum += c[an][2*h] + c[an][2*h + 1];
            }
            sum += __shfl_xor_sync(0xffffffffu, sum, 1);
            sum += __shfl_xor_sync(0xffffffffu, sum, 2);
            lst[h] = lst[h] * corr + sum;
            mst[h] = mnew;
            #pragma unroll
            for (int an = 0; an < 8; an++) {
                o[an][2*h]     *= corr;
                o[an][2*h + 1] *= corr;
            }
        }

        // --- O += P V: P A-fragments built by in-register lane permute.
        #pragma unroll
        for (int ko = 0; ko < 8; ko++) {
            float v00 = __shfl_sync(0xffffffffu, c[ko][0], src0);
            float v01 = __shfl_sync(0xffffffffu, c[ko][1], src0);
            float v10 = __shfl_sync(0xffffffffu, c[ko][2], src0);
            float v11 = __shfl_sync(0xffffffffu, c[ko][3], src0);
            float w00 = __shfl_sync(0xffffffffu, c[ko][0], src2);
            float w01 = __shfl_sync(0xffffffffu, c[ko][1], src2);
            float w10 = __shfl_sync(0xffffffffu, c[ko][2], src2);
            float w11 = __shfl_sync(0xffffffffu, c[ko][3], src2);
            uint32_t pf[4];
            pf[0] = tf32b((t3 & 1) ? v01 : v00);
            pf[1] = tf32b((t3 & 1) ? v11 : v10);
            pf[2] = tf32b((t3 & 1) ? w01 : w00);
            pf[3] = tf32b((t3 & 1) ? w11 : w10);

            uint32_t b[8][2];
            #pragma unroll
            for (int p = 0; p < 4; p++) {
                int row = p * 16 + ((lane >> 4) & 1) * 8 + (lane & 7);
                int col = ko * 8 + ((lane >> 3) & 1) * 4;
                uint32_t t4[4];
                ldsm_x4(t4, smem_u32(&Vts[row * ATSTR + col]));
                b[2*p    ][0] = t4[0]; b[2*p    ][1] = t4[1];
                b[2*p + 1][0] = t4[2]; b[2*p + 1][1] = t4[3];
            }
            #pragma unroll
            for (int an = 0; an < 8; an++) mma_tf32(o[an], pf, b[an]);
        }
    }

    // --- epilogue: normalize, tf32-round, write [B,T,D]
    const int b  = bh >> 4;
    const int hd = bh & 15;
    const int r0 = w * 16 + (lane >> 2);
    #pragma unroll
    for (int h = 0; h < 2; h++) {
        float inv = 1.0f / lst[h];
        int t = qt * 64 + r0 + h * 8;
        float* orow = &g_att[((size_t)b * TSEQ + t) * DMOD + hd * HDIM];
        #pragma unroll
        for (int an = 0; an < 8; an++) {
            int d = an * 8 + t3 * 2;
            float2 v;
            v.x = tf32r(o[an][2*h]     * inv);
            v.y = tf32r(o[an][2*h + 1] * inv);
            *(float2*)&orow[d] = v;
        }
    }
}

__global__ __launch_bounds__(128) void attn_mma() {
    float* Kbuf = dynsm;               // [2][ATILE]
    float* Vbuf = dynsm + 2 * ATILE;   // [2][ATILE]
    const int bh = blockIdx.y;
    attn_pass(NQT - 1 - blockIdx.x, bh, Kbuf, Vbuf);   // long pass first
    attn_pass(blockIdx.x,           bh, Kbuf, Vbuf);   // short pass second
}

// ---------------------------------------------------------------------------
extern "C" void kernel_launch(void* const* d_in, const int* in_sizes, int n_in,
                              void* d_out, int out_size) {
    (void)in_sizes; (void)n_in; (void)out_size;
    const float* x     = (const float*)d_in[0];
    const float* Wkqv  = (const float*)d_in[1];
    const float* bkqv  = (const float*)d_in[2];
    const float* Wproj = (const float*)d_in[3];
    const float* bproj = (const float*)d_in[4];
    float* out = (float*)d_out;

    cudaFuncSetAttribute(attn_mma, cudaFuncAttributeMaxDynamicSharedMemorySize, ATT_SMEM);

    prep_k<<<4096 + 3072 + 1024, 256>>>(x, Wkqv, Wproj);

    gemm_qkv_mma <<<dim3(3*DMOD/128, MTOK/128), 256>>>(bkqv);
    attn_mma     <<<dim3(NQT/2, BSZ*NH),        128, ATT_SMEM>>>();
    gemm_proj_mma<<<dim3(DMOD/128,  MTOK/128),  256>>>(bproj, out);
}

// round 15
// speedup vs baseline: 1.0709x; 1.0516x over previous
#include <cuda_runtime.h>
#include <cstdint>
#include <math.h>

#define BSZ   2
#define TSEQ  2048
#define DMOD  1024
#define NH    16
#define HDIM  64
#define MTOK  (BSZ*TSEQ)      /* 4096 */
#define NQT   (TSEQ/64)       /* 32 q-tiles */
#define NCTA_ATT 296          /* 148 SMs x 2 CTAs/SM -> exactly one wave */
#define NPASS (NQT * BSZ * NH)/* 1024 attention passes */

// Scratch (device globals — no allocations allowed)
__device__ float g_q[(size_t)BSZ*NH*TSEQ*HDIM];   // [B,H,T,64] (Q scaled by log2e/8, tf32)
__device__ float g_k[(size_t)BSZ*NH*TSEQ*HDIM];   // [B,H,T,64] (tf32)
__device__ float g_vT[(size_t)BSZ*NH*HDIM*TSEQ];  // [B,H,64,T] (tf32, t-major!)
__device__ float g_att[(size_t)MTOK*DMOD];        // [B,T,D] (tf32-rounded)
__device__ float g_xr[(size_t)MTOK*DMOD];         // x, tf32-rounded
__device__ float g_wkqvT[(size_t)3*DMOD*DMOD];    // W_kqv^T  [3072,1024] (tf32)
__device__ float g_wprojT[(size_t)DMOD*DMOD];     // W_proj^T [1024,1024] (tf32)

extern __shared__ float dynsm[];

// ===========================================================================
// Helpers
// ===========================================================================
__device__ __forceinline__ uint32_t smem_u32(const void* p) {
    uint32_t a;
    asm("{ .reg .u64 t; cvta.to.shared.u64 t, %1; cvt.u32.u64 %0, t; }"
        : "=r"(a) : "l"(p));
    return a;
}
__device__ __forceinline__ float tf32r(float x) {
    uint32_t u;
    asm("cvt.rna.tf32.f32 %0, %1;" : "=r"(u) : "f"(x));
    return __uint_as_float(u);
}
__device__ __forceinline__ uint32_t tf32b(float x) {
    uint32_t u;
    asm("cvt.rna.tf32.f32 %0, %1;" : "=r"(u) : "f"(x));
    return u;
}
__device__ __forceinline__ void cp_async16(uint32_t sdst, const void* gsrc) {
    asm volatile("cp.async.cg.shared.global [%0], [%1], 16;" :: "r"(sdst), "l"(gsrc));
}
#define CP_COMMIT() asm volatile("cp.async.commit_group;" ::: "memory")
#define CP_WAIT(n)  asm volatile("cp.async.wait_group %0;" :: "n"(n) : "memory")
__device__ __forceinline__ void ldsm_x4(uint32_t* r, uint32_t addr) {
    asm volatile("ldmatrix.sync.aligned.m8n8.x4.b16 {%0,%1,%2,%3}, [%4];"
                 : "=r"(r[0]), "=r"(r[1]), "=r"(r[2]), "=r"(r[3]) : "r"(addr));
}
__device__ __forceinline__ void mma_tf32(float* c, const uint32_t* a, const uint32_t* b) {
    asm volatile("mma.sync.aligned.m16n8k8.row.col.f32.tf32.tf32.f32 "
                 "{%0,%1,%2,%3}, {%4,%5,%6,%7}, {%8,%9}, {%0,%1,%2,%3};"
                 : "+f"(c[0]), "+f"(c[1]), "+f"(c[2]), "+f"(c[3])
                 : "r"(a[0]), "r"(a[1]), "r"(a[2]), "r"(a[3]), "r"(b[0]), "r"(b[1]));
}
// Bare hardware exp2 (no argument FMUL — scores are pre-scaled by log2e).
__device__ __forceinline__ float ex2(float x) {
    float r;
    asm("ex2.approx.f32 %0, %1;" : "=f"(r) : "f"(x));
    return r;
}

// ===========================================================================
// Fused pre-pass: tf32-round x; transpose+round both weight matrices.
// Flattened grid: [0,4096) round_x, [4096,7168) W_kqv^T, [7168,8192) W_proj^T.
// ===========================================================================
__global__ __launch_bounds__(256) void prep_k(const float* __restrict__ x,
                                              const float* __restrict__ Wkqv,
                                              const float* __restrict__ Wproj) {
    __shared__ float t[32][33];
    const int bx = blockIdx.x;
    if (bx < 4096) {
        int i = (bx * 256 + threadIdx.x) * 4;
        float4 v = *(const float4*)&x[i];
        v.x = tf32r(v.x); v.y = tf32r(v.y); v.z = tf32r(v.z); v.w = tf32r(v.w);
        *(float4*)&g_xr[i] = v;
        return;
    }
    const float* S;
    float* D;
    int gx, gy, R, C;
    if (bx < 4096 + 3072) {
        int b2 = bx - 4096;
        S = Wkqv; D = g_wkqvT; R = DMOD; C = 3*DMOD;
        gx = b2 % 96; gy = b2 / 96;
    } else {
        int b3 = bx - (4096 + 3072);
        S = Wproj; D = g_wprojT; R = DMOD; C = DMOD;
        gx = b3 % 32; gy = b3 / 32;
    }
    const int txx = threadIdx.x & 31;
    const int tyy = threadIdx.x >> 5;
    const int xx  = gx * 32 + txx;
    const int y0  = gy * 32;
    #pragma unroll
    for (int i = tyy; i < 32; i += 8)
        t[i][txx] = S[(size_t)(y0 + i) * C + xx];
    __syncthreads();
    const int xo  = y0 + txx;
    const int yo0 = gx * 32;
    #pragma unroll
    for (int i = tyy; i < 32; i += 8)
        D[(size_t)(yo0 + i) * R + xo] = tf32r(t[txx][i]);
}

// ===========================================================================
// tf32 mma.sync GEMM body — EXACT R5/R9 proven structure. DO NOT TOUCH.
// CTA 128x128, 8 warps (2m x 4n), warp tile 64x32, KC=16, 2-stage, static smem.
// ===========================================================================
#define KC 16
#define SSTR 20

__device__ __forceinline__ void gemm_load_stage(const float* __restrict__ A,
                                                const float* __restrict__ BT,
                                                float* As, float* Bs,
                                                int m0, int n0, int K, int k0) {
    const int tid = threadIdx.x;
    #pragma unroll
    for (int r = 0; r < 2; r++) {
        int idx = tid + r * 256;
        int row = idx >> 2, c4 = idx & 3;
        cp_async16(smem_u32(&As[row * SSTR + c4 * 4]),
                   &A[(size_t)(m0 + row) * K + k0 + c4 * 4]);
        cp_async16(smem_u32(&Bs[row * SSTR + c4 * 4]),
                   &BT[(size_t)(n0 + row) * K + k0 + c4 * 4]);
    }
    CP_COMMIT();
}

__device__ __forceinline__ void gemm_compute_stage(const float* As, const float* Bs,
                                                   int wm, int wn, int lane,
                                                   float c[4][4][4]) {
    #pragma unroll
    for (int oct = 0; oct < 2; oct++) {
        const int k0 = oct * 8;
        uint32_t a[4][4];
        #pragma unroll
        for (int am = 0; am < 4; am++) {
            int row = wm + am * 16 + ((lane >> 3) & 1) * 8 + (lane & 7);
            int col = k0 + (lane >> 4) * 4;
            ldsm_x4(a[am], smem_u32(&As[row * SSTR + col]));
        }
        uint32_t b[4][2];
        #pragma unroll
        for (int p = 0; p < 2; p++) {
            int row = wn + p * 16 + ((lane >> 4) & 1) * 8 + (lane & 7);
            int col = k0 + ((lane >> 3) & 1) * 4;
            uint32_t r[4];
            ldsm_x4(r, smem_u32(&Bs[row * SSTR + col]));
            b[2*p    ][0] = r[0]; b[2*p    ][1] = r[1];
            b[2*p + 1][0] = r[2]; b[2*p + 1][1] = r[3];
        }
        #pragma unroll
        for (int am = 0; am < 4; am++)
            #pragma unroll
            for (int an = 0; an < 4; an++)
                mma_tf32(c[am][an], a[am], b[an]);
    }
}

__device__ __forceinline__ void gemm_mma_body(const float* __restrict__ A,
                                              const float* __restrict__ BT,
                                              int m0, int n0, int K,
                                              float c[4][4][4]) {
    __shared__ __align__(16) float As[2][128 * SSTR];
    __shared__ __align__(16) float Bs[2][128 * SSTR];
    const int lane = threadIdx.x & 31;
    const int wid  = threadIdx.x >> 5;
    const int wm = (wid & 1) * 64;
    const int wn = (wid >> 1) * 32;

    gemm_load_stage(A, BT, As[0], Bs[0], m0, n0, K, 0);
    const int nk = K / KC;
    for (int kt = 0; kt < nk; kt++) {
        if (kt + 1 < nk) {
            gemm_load_stage(A, BT, As[(kt+1)&1], Bs[(kt+1)&1], m0, n0, K, (kt+1)*KC);
            CP_WAIT(1);
        } else {
            CP_WAIT(0);
        }
        __syncthreads();
        gemm_compute_stage(As[kt&1], Bs[kt&1], wm, wn, lane, c);
        __syncthreads();
    }
}

// QKV GEMM epilogue: q/k -> [B,H,T,64] tf32; v -> g_vT [B,H,64,T].
// Q is scaled by log2(e)/8 so attention scores land in the exp2 domain.
#define QSCALE (0.125f * 1.44269504088896f)

__global__ __launch_bounds__(256) void gemm_qkv_mma(const float* __restrict__ bias) {
    float c[4][4][4] = {};
    const int m0 = blockIdx.y * 128, n0 = blockIdx.x * 128;
    gemm_mma_body(g_xr, g_wkqvT, m0, n0, DMOD, c);
    const int lane = threadIdx.x & 31;
    const int wid  = threadIdx.x >> 5;
    const int wm = (wid & 1) * 64, wn = (wid >> 1) * 32;
    #pragma unroll
    for (int an = 0; an < 4; an++) {
        int cb = n0 + wn + an * 8 + (lane & 3) * 2;
        int which = cb >> 10;
        int h  = (cb >> 6) & (NH - 1);
        int ch = cb & 63;
        float2 bb = *(const float2*)&bias[cb];
        #pragma unroll
        for (int am = 0; am < 4; am++) {
            #pragma unroll
            for (int hf = 0; hf < 2; hf++) {
                int m = m0 + wm + am * 16 + (lane >> 2) + hf * 8;
                int b = m >> 11, t = m & (TSEQ - 1);
                float vx = c[am][an][2*hf + 0] + bb.x;
                float vy = c[am][an][2*hf + 1] + bb.y;
                if (which == 2) {
                    size_t vb = (size_t)(b * NH + h) * HDIM;
                    g_vT[(vb + ch    ) * TSEQ + t] = tf32r(vx);
                    g_vT[(vb + ch + 1) * TSEQ + t] = tf32r(vy);
                } else {
                    float* dst = (which == 0) ? g_q : g_k;
                    float qs = (which == 0) ? QSCALE : 1.0f;
                    float2 v;
                    v.x = tf32r(vx * qs);
                    v.y = tf32r(vy * qs);
                    *(float2*)&dst[((size_t)(b * NH + h) * TSEQ + t) * HDIM + ch] = v;
                }
            }
        }
    }
}

// Output projection: out = g_att @ WprojT^T + b
__global__ __launch_bounds__(256) void gemm_proj_mma(const float* __restrict__ bias,
                                                     float* __restrict__ C) {
    float c[4][4][4] = {};
    const int m0 = blockIdx.y * 128, n0 = blockIdx.x * 128;
    gemm_mma_body(g_att, g_wprojT, m0, n0, DMOD, c);
    const int lane = threadIdx.x & 31;
    const int wid  = threadIdx.x >> 5;
    const int wm = (wid & 1) * 64, wn = (wid >> 1) * 32;
    #pragma unroll
    for (int an = 0; an < 4; an++) {
        int cb = n0 + wn + an * 8 + (lane & 3) * 2;
        float2 bb = *(const float2*)&bias[cb];
        #pragma unroll
        for (int am = 0; am < 4; am++) {
            #pragma unroll
            for (int hf = 0; hf < 2; hf++) {
                int m = m0 + wm + am * 16 + (lane >> 2) + hf * 8;
                float2 v;
                v.x = c[am][an][2*hf + 0] + bb.x;
                v.y = c[am][an][2*hf + 1] + bb.y;
                *(float2*)&C[(size_t)m * DMOD + cb] = v;
            }
        }
    }
}

// ===========================================================================
// mma.sync flash attention — R14 body (exp2-domain softmax), now with a
// single-wave balanced static schedule: 296 CTAs (= 148 SMs x 2 slots),
// snake order over 1024 (qt,bh) passes sorted by descending qt.
// Per-CTA cost lands in [54,59] tiles vs 66 for the old paired grid.
// ===========================================================================
#define ATSTR 68
#define ATILE (64 * ATSTR)
#define ATT_SMEM (4 * ATILE * 4)

__device__ __forceinline__ void attn_prefetch(const float* __restrict__ Kb,
                                              const float* __restrict__ VTb,
                                              float* Kd, float* Vd, int kt) {
    const int tid = threadIdx.x;
    #pragma unroll
    for (int r = 0; r < 8; r++) {
        int f = tid + r * 128;
        int row = f >> 4, c4 = f & 15;
        cp_async16(smem_u32(&Kd[row * ATSTR + c4 * 4]),
                   Kb + ((size_t)kt * 64 + row) * HDIM + c4 * 4);
        cp_async16(smem_u32(&Vd[row * ATSTR + c4 * 4]),
                   VTb + (size_t)row * TSEQ + kt * 64 + c4 * 4);
    }
    CP_COMMIT();
}

__device__ void attn_pass(int qt, int bh, float* Kbuf, float* Vbuf) {
    const int tid = threadIdx.x;
    const int lane = tid & 31;
    const int w    = tid >> 5;

    const float* Qb  = g_q  + ((size_t)bh * TSEQ + (size_t)qt * 64) * HDIM;
    const float* Kb  = g_k  + (size_t)bh * TSEQ * HDIM;
    const float* VTb = g_vT + (size_t)bh * HDIM * TSEQ;

    __syncthreads();   // prior pass fully done with smem
    // Stage Q through Kbuf[1], load A-fragments to registers
    {
        const float4* Qt = (const float4*)Qb;
        float* Qs = Kbuf + ATILE;
        #pragma unroll
        for (int r = 0; r < 8; r++) {
            int f = tid + r * 128;
            int row = f >> 4, c4 = f & 15;
            *(float4*)&Qs[row * ATSTR + c4 * 4] = Qt[f];
        }
    }
    __syncthreads();
    uint32_t qf[8][4];
    {
        const float* Qs = Kbuf + ATILE;
        int row = w * 16 + ((lane >> 3) & 1) * 8 + (lane & 7);
        #pragma unroll
        for (int oct = 0; oct < 8; oct++)
            ldsm_x4(qf[oct], smem_u32(&Qs[row * ATSTR + oct * 8 + (lane >> 4) * 4]));
    }

    // Prefetch k-tile 0 into buffer 0 (doesn't touch Kbuf[1] holding Q)
    attn_prefetch(Kb, VTb, Kbuf, Vbuf, 0);

    float mst[2] = {-1e30f, -1e30f}, lst[2] = {0.f, 0.f};
    float o[8][4];
    #pragma unroll
    for (int an = 0; an < 8; an++)
        #pragma unroll
        for (int e = 0; e < 4; e++) o[an][e] = 0.f;

    const int t3   = lane & 3;
    const int src0 = (lane & ~3) | (t3 >> 1);
    const int src2 = src0 + 2;

    for (int kt = 0; kt <= qt; kt++) {
        CP_WAIT(0);
        __syncthreads();   // stage kt visible; all warps done with buf[(kt+1)&1]
        if (kt + 1 <= qt)
            attn_prefetch(Kb, VTb, Kbuf + ((kt+1)&1)*ATILE, Vbuf + ((kt+1)&1)*ATILE, kt+1);

        const float* Ks  = Kbuf + (kt & 1) * ATILE;
        const float* Vts = Vbuf + (kt & 1) * ATILE;

        // --- S = Q K^T (warp: 16q x 64k); scores already in log2 units
        float c[8][4];
        #pragma unroll
        for (int an = 0; an < 8; an++)
            #pragma unroll
            for (int e = 0; e < 4; e++) c[an][e] = 0.f;
        #pragma unroll
        for (int oct = 0; oct < 8; oct++) {
            uint32_t b[8][2];
            #pragma unroll
            for (int p = 0; p < 4; p++) {
                int row = p * 16 + ((lane >> 4) & 1) * 8 + (lane & 7);
                int col = oct * 8 + ((lane >> 3) & 1) * 4;
                uint32_t t4[4];
                ldsm_x4(t4, smem_u32(&Ks[row * ATSTR + col]));
                b[2*p    ][0] = t4[0]; b[2*p    ][1] = t4[1];
                b[2*p + 1][0] = t4[2]; b[2*p + 1][1] = t4[3];
            }
            #pragma unroll
            for (int an = 0; an < 8; an++) mma_tf32(c[an], qf[oct], b[an]);
        }

        // --- causal mask (diagonal tile only)
        if (kt == qt) {
            int r0 = w * 16 + (lane >> 2);
            #pragma unroll
            for (int an = 0; an < 8; an++) {
                int k0 = an * 8 + t3 * 2;
                if (k0     > r0)     c[an][0] = -1e30f;
                if (k0 + 1 > r0)     c[an][1] = -1e30f;
                if (k0     > r0 + 8) c[an][2] = -1e30f;
                if (k0 + 1 > r0 + 8) c[an][3] = -1e30f;
            }
        }

        // --- online softmax (exp2 domain: bare MUFU.EX2)
        #pragma unroll
        for (int h = 0; h < 2; h++) {
            float mt = -1e30f;
            #pragma unroll
            for (int an = 0; an < 8; an++)
                mt = fmaxf(mt, fmaxf(c[an][2*h], c[an][2*h + 1]));
            mt = fmaxf(mt, __shfl_xor_sync(0xffffffffu, mt, 1));
            mt = fmaxf(mt, __shfl_xor_sync(0xffffffffu, mt, 2));
            float mnew = fmaxf(mst[h], mt);
            float corr = ex2(mst[h] - mnew);
            float sum = 0.f;
            #pragma unroll
            for (int an = 0; an < 8; an++) {
                c[an][2*h]     = ex2(c[an][2*h]     - mnew);
                c[an][2*h + 1] = ex2(c[an][2*h + 1] - mnew);
                sum += c[an][2*h] + c[an][2*h + 1];
            }
            sum += __shfl_xor_sync(0xffffffffu, sum, 1);
            sum += __shfl_xor_sync(0xffffffffu, sum, 2);
            lst[h] = lst[h] * corr + sum;
            mst[h] = mnew;
            #pragma unroll
            for (int an = 0; an < 8; an++) {
                o[an][2*h]     *= corr;
                o[an][2*h + 1] *= corr;
            }
        }

        // --- O += P V: P A-fragments built by in-register lane permute.
        #pragma unroll
        for (int ko = 0; ko < 8; ko++) {
            float v00 = __shfl_sync(0xffffffffu, c[ko][0], src0);
            float v01 = __shfl_sync(0xffffffffu, c[ko][1], src0);
            float v10 = __shfl_sync(0xffffffffu, c[ko][2], src0);
            float v11 = __shfl_sync(0xffffffffu, c[ko][3], src0);
            float w00 = __shfl_sync(0xffffffffu, c[ko][0], src2);
            float w01 = __shfl_sync(0xffffffffu, c[ko][1], src2);
            float w10 = __shfl_sync(0xffffffffu, c[ko][2], src2);
            float w11 = __shfl_sync(0xffffffffu, c[ko][3], src2);
            uint32_t pf[4];
            pf[0] = tf32b((t3 & 1) ? v01 : v00);
            pf[1] = tf32b((t3 & 1) ? v11 : v10);
            pf[2] = tf32b((t3 & 1) ? w01 : w00);
            pf[3] = tf32b((t3 & 1) ? w11 : w10);

            uint32_t b[8][2];
            #pragma unroll
            for (int p = 0; p < 4; p++) {
                int row = p * 16 + ((lane >> 4) & 1) * 8 + (lane & 7);
                int col = ko * 8 + ((lane >> 3) & 1) * 4;
                uint32_t t4[4];
                ldsm_x4(t4, smem_u32(&Vts[row * ATSTR + col]));
                b[2*p    ][0] = t4[0]; b[2*p    ][1] = t4[1];
                b[2*p + 1][0] = t4[2]; b[2*p + 1][1] = t4[3];
            }
            #pragma unroll
            for (int an = 0; an < 8; an++) mma_tf32(o[an], pf, b[an]);
        }
    }

    // --- epilogue: normalize, tf32-round, write [B,T,D]
    const int b  = bh >> 4;
    const int hd = bh & 15;
    const int r0 = w * 16 + (lane >> 2);
    #pragma unroll
    for (int h = 0; h < 2; h++) {
        float inv = 1.0f / lst[h];
        int t = qt * 64 + r0 + h * 8;
        float* orow = &g_att[((size_t)b * TSEQ + t) * DMOD + hd * HDIM];
        #pragma unroll
        for (int an = 0; an < 8; an++) {
            int d = an * 8 + t3 * 2;
            float2 v;
            v.x = tf32r(o[an][2*h]     * inv);
            v.y = tf32r(o[an][2*h + 1] * inv);
            *(float2*)&orow[d] = v;
        }
    }
}

__global__ __launch_bounds__(128) void attn_mma() {
    float* Kbuf = dynsm;               // [2][ATILE]
    float* Vbuf = dynsm + 2 * ATILE;   // [2][ATILE]
    const int k = blockIdx.x;          // 0..NCTA_ATT-1
    // Snake schedule over NPASS items ordered by descending qt:
    // item idx -> qt = NQT-1 - idx/32 (cost qt+1), bh = idx%32.
    #pragma unroll
    for (int r = 0; r < (NPASS + NCTA_ATT - 1) / NCTA_ATT; r++) {
        int idx = r * NCTA_ATT + ((r & 1) ? (NCTA_ATT - 1 - k) : k);
        if (idx < NPASS) {
            int qt = (NQT - 1) - (idx >> 5);
            int bh = idx & 31;
            attn_pass(qt, bh, Kbuf, Vbuf);
        }
    }
}

// ---------------------------------------------------------------------------
extern "C" void kernel_launch(void* const* d_in, const int* in_sizes, int n_in,
                              void* d_out, int out_size) {
    (void)in_sizes; (void)n_in; (void)out_size;
    const float* x     = (const float*)d_in[0];
    const float* Wkqv  = (const float*)d_in[1];
    const float* bkqv  = (const float*)d_in[2];
    const float* Wproj = (const float*)d_in[3];
    const float* bproj = (const float*)d_in[4];
    float* out = (float*)d_out;

    cudaFuncSetAttribute(attn_mma, cudaFuncAttributeMaxDynamicSharedMemorySize, ATT_SMEM);

    prep_k<<<4096 + 3072 + 1024, 256>>>(x, Wkqv, Wproj);

    gemm_qkv_mma <<<dim3(3*DMOD/128, MTOK/128), 256>>>(bkqv);
    attn_mma     <<<NCTA_ATT,                   128, ATT_SMEM>>>();
    gemm_proj_mma<<<dim3(DMOD/128,  MTOK/128),  256>>>(bproj, out);
}

// round 16
// speedup vs baseline: 1.1036x; 1.0305x over previous
#include <cuda_runtime.h>
#include <cstdint>
#include <math.h>

#define BSZ   2
#define TSEQ  2048
#define DMOD  1024
#define NH    16
#define HDIM  64
#define MTOK  (BSZ*TSEQ)      /* 4096 */
#define NQT   (TSEQ/64)       /* 32 q-tiles */
#define NCTA_ATT 296          /* 148 SMs x 2 CTAs/SM -> exactly one wave */
#define NPASS (NQT * BSZ * NH)/* 1024 attention passes */

// Scratch (device globals — no allocations allowed)
__device__ float g_q[(size_t)BSZ*NH*TSEQ*HDIM];   // [B,H,T,64] (Q scaled by log2e/8, tf32)
__device__ float g_k[(size_t)BSZ*NH*TSEQ*HDIM];   // [B,H,T,64] (tf32)
__device__ float g_vT[(size_t)BSZ*NH*HDIM*TSEQ];  // [B,H,64,T] (tf32, t-major,
                                                  //  t PERMUTED by sigma within 8-groups)
__device__ float g_att[(size_t)MTOK*DMOD];        // [B,T,D] (tf32-rounded)
__device__ float g_xr[(size_t)MTOK*DMOD];         // x, tf32-rounded
__device__ float g_wkqvT[(size_t)3*DMOD*DMOD];    // W_kqv^T  [3072,1024] (tf32)
__device__ float g_wprojT[(size_t)DMOD*DMOD];     // W_proj^T [1024,1024] (tf32)

extern __shared__ float dynsm[];

// ===========================================================================
// Helpers
// ===========================================================================
__device__ __forceinline__ uint32_t smem_u32(const void* p) {
    uint32_t a;
    asm("{ .reg .u64 t; cvta.to.shared.u64 t, %1; cvt.u32.u64 %0, t; }"
        : "=r"(a) : "l"(p));
    return a;
}
__device__ __forceinline__ float tf32r(float x) {
    uint32_t u;
    asm("cvt.rna.tf32.f32 %0, %1;" : "=r"(u) : "f"(x));
    return __uint_as_float(u);
}
__device__ __forceinline__ uint32_t tf32b(float x) {
    uint32_t u;
    asm("cvt.rna.tf32.f32 %0, %1;" : "=r"(u) : "f"(x));
    return u;
}
__device__ __forceinline__ void cp_async16(uint32_t sdst, const void* gsrc) {
    asm volatile("cp.async.cg.shared.global [%0], [%1], 16;" :: "r"(sdst), "l"(gsrc));
}
#define CP_COMMIT() asm volatile("cp.async.commit_group;" ::: "memory")
#define CP_WAIT(n)  asm volatile("cp.async.wait_group %0;" :: "n"(n) : "memory")
__device__ __forceinline__ void ldsm_x4(uint32_t* r, uint32_t addr) {
    asm volatile("ldmatrix.sync.aligned.m8n8.x4.b16 {%0,%1,%2,%3}, [%4];"
                 : "=r"(r[0]), "=r"(r[1]), "=r"(r[2]), "=r"(r[3]) : "r"(addr));
}
__device__ __forceinline__ void mma_tf32(float* c, const uint32_t* a, const uint32_t* b) {
    asm volatile("mma.sync.aligned.m16n8k8.row.col.f32.tf32.tf32.f32 "
                 "{%0,%1,%2,%3}, {%4,%5,%6,%7}, {%8,%9}, {%0,%1,%2,%3};"
                 : "+f"(c[0]), "+f"(c[1]), "+f"(c[2]), "+f"(c[3])
                 : "r"(a[0]), "r"(a[1]), "r"(a[2]), "r"(a[3]), "r"(b[0]), "r"(b[1]));
}
// Bare hardware exp2 (no argument FMUL — scores are pre-scaled by log2e).
__device__ __forceinline__ float ex2(float x) {
    float r;
    asm("ex2.approx.f32 %0, %1;" : "=f"(r) : "f"(x));
    return r;
}

// ===========================================================================
// Fused pre-pass: tf32-round x; transpose+round both weight matrices.
// Flattened grid: [0,4096) round_x, [4096,7168) W_kqv^T, [7168,8192) W_proj^T.
// ===========================================================================
__global__ __launch_bounds__(256) void prep_k(const float* __restrict__ x,
                                              const float* __restrict__ Wkqv,
                                              const float* __restrict__ Wproj) {
    __shared__ float t[32][33];
    const int bx = blockIdx.x;
    if (bx < 4096) {
        int i = (bx * 256 + threadIdx.x) * 4;
        float4 v = *(const float4*)&x[i];
        v.x = tf32r(v.x); v.y = tf32r(v.y); v.z = tf32r(v.z); v.w = tf32r(v.w);
        *(float4*)&g_xr[i] = v;
        return;
    }
    const float* S;
    float* D;
    int gx, gy, R, C;
    if (bx < 4096 + 3072) {
        int b2 = bx - 4096;
        S = Wkqv; D = g_wkqvT; R = DMOD; C = 3*DMOD;
        gx = b2 % 96; gy = b2 / 96;
    } else {
        int b3 = bx - (4096 + 3072);
        S = Wproj; D = g_wprojT; R = DMOD; C = DMOD;
        gx = b3 % 32; gy = b3 / 32;
    }
    const int txx = threadIdx.x & 31;
    const int tyy = threadIdx.x >> 5;
    const int xx  = gx * 32 + txx;
    const int y0  = gy * 32;
    #pragma unroll
    for (int i = tyy; i < 32; i += 8)
        t[i][txx] = S[(size_t)(y0 + i) * C + xx];
    __syncthreads();
    const int xo  = y0 + txx;
    const int yo0 = gx * 32;
    #pragma unroll
    for (int i = tyy; i < 32; i += 8)
        D[(size_t)(yo0 + i) * R + xo] = tf32r(t[txx][i]);
}

// ===========================================================================
// tf32 mma.sync GEMM body — EXACT R5/R9 proven structure. DO NOT TOUCH.
// CTA 128x128, 8 warps (2m x 4n), warp tile 64x32, KC=16, 2-stage, static smem.
// ===========================================================================
#define KC 16
#define SSTR 20

__device__ __forceinline__ void gemm_load_stage(const float* __restrict__ A,
                                                const float* __restrict__ BT,
                                                float* As, float* Bs,
                                                int m0, int n0, int K, int k0) {
    const int tid = threadIdx.x;
    #pragma unroll
    for (int r = 0; r < 2; r++) {
        int idx = tid + r * 256;
        int row = idx >> 2, c4 = idx & 3;
        cp_async16(smem_u32(&As[row * SSTR + c4 * 4]),
                   &A[(size_t)(m0 + row) * K + k0 + c4 * 4]);
        cp_async16(smem_u32(&Bs[row * SSTR + c4 * 4]),
                   &BT[(size_t)(n0 + row) * K + k0 + c4 * 4]);
    }
    CP_COMMIT();
}

__device__ __forceinline__ void gemm_compute_stage(const float* As, const float* Bs,
                                                   int wm, int wn, int lane,
                                                   float c[4][4][4]) {
    #pragma unroll
    for (int oct = 0; oct < 2; oct++) {
        const int k0 = oct * 8;
        uint32_t a[4][4];
        #pragma unroll
        for (int am = 0; am < 4; am++) {
            int row = wm + am * 16 + ((lane >> 3) & 1) * 8 + (lane & 7);
            int col = k0 + (lane >> 4) * 4;
            ldsm_x4(a[am], smem_u32(&As[row * SSTR + col]));
        }
        uint32_t b[4][2];
        #pragma unroll
        for (int p = 0; p < 2; p++) {
            int row = wn + p * 16 + ((lane >> 4) & 1) * 8 + (lane & 7);
            int col = k0 + ((lane >> 3) & 1) * 4;
            uint32_t r[4];
            ldsm_x4(r, smem_u32(&Bs[row * SSTR + col]));
            b[2*p    ][0] = r[0]; b[2*p    ][1] = r[1];
            b[2*p + 1][0] = r[2]; b[2*p + 1][1] = r[3];
        }
        #pragma unroll
        for (int am = 0; am < 4; am++)
            #pragma unroll
            for (int an = 0; an < 4; an++)
                mma_tf32(c[am][an], a[am], b[an]);
    }
}

__device__ __forceinline__ void gemm_mma_body(const float* __restrict__ A,
                                              const float* __restrict__ BT,
                                              int m0, int n0, int K,
                                              float c[4][4][4]) {
    __shared__ __align__(16) float As[2][128 * SSTR];
    __shared__ __align__(16) float Bs[2][128 * SSTR];
    const int lane = threadIdx.x & 31;
    const int wid  = threadIdx.x >> 5;
    const int wm = (wid & 1) * 64;
    const int wn = (wid >> 1) * 32;

    gemm_load_stage(A, BT, As[0], Bs[0], m0, n0, K, 0);
    const int nk = K / KC;
    for (int kt = 0; kt < nk; kt++) {
        if (kt + 1 < nk) {
            gemm_load_stage(A, BT, As[(kt+1)&1], Bs[(kt+1)&1], m0, n0, K, (kt+1)*KC);
            CP_WAIT(1);
        } else {
            CP_WAIT(0);
        }
        __syncthreads();
        gemm_compute_stage(As[kt&1], Bs[kt&1], wm, wn, lane, c);
        __syncthreads();
    }
}

// QKV GEMM epilogue: q/k -> [B,H,T,64] tf32; v -> g_vT [B,H,64,T] with the
// token index PERMUTED within each 8-group: sigma(t) = t/2 for even t,
// 4 + t/2 for odd t. This makes the attention S-accumulator registers land
// exactly in PV A-fragment order (no lane shuffles in the attention hot loop).
// Q is scaled by log2(e)/8 so attention scores land in the exp2 domain.
#define QSCALE (0.125f * 1.44269504088896f)

__global__ __launch_bounds__(256) void gemm_qkv_mma(const float* __restrict__ bias) {
    float c[4][4][4] = {};
    const int m0 = blockIdx.y * 128, n0 = blockIdx.x * 128;
    gemm_mma_body(g_xr, g_wkqvT, m0, n0, DMOD, c);
    const int lane = threadIdx.x & 31;
    const int wid  = threadIdx.x >> 5;
    const int wm = (wid & 1) * 64, wn = (wid >> 1) * 32;
    #pragma unroll
    for (int an = 0; an < 4; an++) {
        int cb = n0 + wn + an * 8 + (lane & 3) * 2;
        int which = cb >> 10;
        int h  = (cb >> 6) & (NH - 1);
        int ch = cb & 63;
        float2 bb = *(const float2*)&bias[cb];
        #pragma unroll
        for (int am = 0; am < 4; am++) {
            #pragma unroll
            for (int hf = 0; hf < 2; hf++) {
                int m = m0 + wm + am * 16 + (lane >> 2) + hf * 8;
                int b = m >> 11, t = m & (TSEQ - 1);
                float vx = c[am][an][2*hf + 0] + bb.x;
                float vy = c[am][an][2*hf + 1] + bb.y;
                if (which == 2) {
                    // sigma permutation within the 8-token group
                    int tp = (t & ~7) | (((t & 7) >> 1) + (t & 1) * 4);
                    size_t vb = (size_t)(b * NH + h) * HDIM;
                    g_vT[(vb + ch    ) * TSEQ + tp] = tf32r(vx);
                    g_vT[(vb + ch + 1) * TSEQ + tp] = tf32r(vy);
                } else {
                    float* dst = (which == 0) ? g_q : g_k;
                    float qs = (which == 0) ? QSCALE : 1.0f;
                    float2 v;
                    v.x = tf32r(vx * qs);
                    v.y = tf32r(vy * qs);
                    *(float2*)&dst[((size_t)(b * NH + h) * TSEQ + t) * HDIM + ch] = v;
                }
            }
        }
    }
}

// Output projection: out = g_att @ WprojT^T + b
__global__ __launch_bounds__(256) void gemm_proj_mma(const float* __restrict__ bias,
                                                     float* __restrict__ C) {
    float c[4][4][4] = {};
    const int m0 = blockIdx.y * 128, n0 = blockIdx.x * 128;
    gemm_mma_body(g_att, g_wprojT, m0, n0, DMOD, c);
    const int lane = threadIdx.x & 31;
    const int wid  = threadIdx.x >> 5;
    const int wm = (wid & 1) * 64, wn = (wid >> 1) * 32;
    #pragma unroll
    for (int an = 0; an < 4; an++) {
        int cb = n0 + wn + an * 8 + (lane & 3) * 2;
        float2 bb = *(const float2*)&bias[cb];
        #pragma unroll
        for (int am = 0; am < 4; am++) {
            #pragma unroll
            for (int hf = 0; hf < 2; hf++) {
                int m = m0 + wm + am * 16 + (lane >> 2) + hf * 8;
                float2 v;
                v.x = c[am][an][2*hf + 0] + bb.x;
                v.y = c[am][an][2*hf + 1] + bb.y;
                *(float2*)&C[(size_t)m * DMOD + cb] = v;
            }
        }
    }
}

// ===========================================================================
// mma.sync flash attention — exp2-domain softmax, single-wave snake schedule,
// and SHUFFLE-FREE PV: V's token axis is pre-permuted (sigma) so the S
// accumulator registers {c0,c2,c1,c3} are directly the PV A-fragment.
// ===========================================================================
#define ATSTR 68
#define ATILE (64 * ATSTR)
#define ATT_SMEM (4 * ATILE * 4)

__device__ __forceinline__ void attn_prefetch(const float* __restrict__ Kb,
                                              const float* __restrict__ VTb,
                                              float* Kd, float* Vd, int kt) {
    const int tid = threadIdx.x;
    #pragma unroll
    for (int r = 0; r < 8; r++) {
        int f = tid + r * 128;
        int row = f >> 4, c4 = f & 15;
        cp_async16(smem_u32(&Kd[row * ATSTR + c4 * 4]),
                   Kb + ((size_t)kt * 64 + row) * HDIM + c4 * 4);
        cp_async16(smem_u32(&Vd[row * ATSTR + c4 * 4]),
                   VTb + (size_t)row * TSEQ + kt * 64 + c4 * 4);
    }
    CP_COMMIT();
}

__device__ void attn_pass(int qt, int bh, float* Kbuf, float* Vbuf) {
    const int tid = threadIdx.x;
    const int lane = tid & 31;
    const int w    = tid >> 5;

    const float* Qb  = g_q  + ((size_t)bh * TSEQ + (size_t)qt * 64) * HDIM;
    const float* Kb  = g_k  + (size_t)bh * TSEQ * HDIM;
    const float* VTb = g_vT + (size_t)bh * HDIM * TSEQ;

    __syncthreads();   // prior pass fully done with smem
    // Stage Q through Kbuf[1], load A-fragments to registers
    {
        const float4* Qt = (const float4*)Qb;
        float* Qs = Kbuf + ATILE;
        #pragma unroll
        for (int r = 0; r < 8; r++) {
            int f = tid + r * 128;
            int row = f >> 4, c4 = f & 15;
            *(float4*)&Qs[row * ATSTR + c4 * 4] = Qt[f];
        }
    }
    __syncthreads();
    uint32_t qf[8][4];
    {
        const float* Qs = Kbuf + ATILE;
        int row = w * 16 + ((lane >> 3) & 1) * 8 + (lane & 7);
        #pragma unroll
        for (int oct = 0; oct < 8; oct++)
            ldsm_x4(qf[oct], smem_u32(&Qs[row * ATSTR + oct * 8 + (lane >> 4) * 4]));
    }

    // Prefetch k-tile 0 into buffer 0 (doesn't touch Kbuf[1] holding Q)
    attn_prefetch(Kb, VTb, Kbuf, Vbuf, 0);

    float mst[2] = {-1e30f, -1e30f}, lst[2] = {0.f, 0.f};
    float o[8][4];
    #pragma unroll
    for (int an = 0; an < 8; an++)
        #pragma unroll
        for (int e = 0; e < 4; e++) o[an][e] = 0.f;

    const int t3 = lane & 3;

    for (int kt = 0; kt <= qt; kt++) {
        CP_WAIT(0);
        __syncthreads();   // stage kt visible; all warps done with buf[(kt+1)&1]
        if (kt + 1 <= qt)
            attn_prefetch(Kb, VTb, Kbuf + ((kt+1)&1)*ATILE, Vbuf + ((kt+1)&1)*ATILE, kt+1);

        const float* Ks  = Kbuf + (kt & 1) * ATILE;
        const float* Vts = Vbuf + (kt & 1) * ATILE;

        // --- S = Q K^T (warp: 16q x 64k); scores already in log2 units
        float c[8][4];
        #pragma unroll
        for (int an = 0; an < 8; an++)
            #pragma unroll
            for (int e = 0; e < 4; e++) c[an][e] = 0.f;
        #pragma unroll
        for (int oct = 0; oct < 8; oct++) {
            uint32_t b[8][2];
            #pragma unroll
            for (int p = 0; p < 4; p++) {
                int row = p * 16 + ((lane >> 4) & 1) * 8 + (lane & 7);
                int col = oct * 8 + ((lane >> 3) & 1) * 4;
                uint32_t t4[4];
                ldsm_x4(t4, smem_u32(&Ks[row * ATSTR + col]));
                b[2*p    ][0] = t4[0]; b[2*p    ][1] = t4[1];
                b[2*p + 1][0] = t4[2]; b[2*p + 1][1] = t4[3];
            }
            #pragma unroll
            for (int an = 0; an < 8; an++) mma_tf32(c[an], qf[oct], b[an]);
        }

        // --- causal mask (diagonal tile only; K is in natural token order)
        if (kt == qt) {
            int r0 = w * 16 + (lane >> 2);
            #pragma unroll
            for (int an = 0; an < 8; an++) {
                int k0 = an * 8 + t3 * 2;
                if (k0     > r0)     c[an][0] = -1e30f;
                if (k0 + 1 > r0)     c[an][1] = -1e30f;
                if (k0     > r0 + 8) c[an][2] = -1e30f;
                if (k0 + 1 > r0 + 8) c[an][3] = -1e30f;
            }
        }

        // --- online softmax (exp2 domain: bare MUFU.EX2)
        #pragma unroll
        for (int h = 0; h < 2; h++) {
            float mt = -1e30f;
            #pragma unroll
            for (int an = 0; an < 8; an++)
                mt = fmaxf(mt, fmaxf(c[an][2*h], c[an][2*h + 1]));
            mt = fmaxf(mt, __shfl_xor_sync(0xffffffffu, mt, 1));
            mt = fmaxf(mt, __shfl_xor_sync(0xffffffffu, mt, 2));
            float mnew = fmaxf(mst[h], mt);
            float corr = ex2(mst[h] - mnew);
            float sum = 0.f;
            #pragma unroll
            for (int an = 0; an < 8; an++) {
                c[an][2*h]     = ex2(c[an][2*h]     - mnew);
                c[an][2*h + 1] = ex2(c[an][2*h + 1] - mnew);
                sum += c[an][2*h] + c[an][2*h + 1];
            }
            sum += __shfl_xor_sync(0xffffffffu, sum, 1);
            sum += __shfl_xor_sync(0xffffffffu, sum, 2);
            lst[h] = lst[h] * corr + sum;
            mst[h] = mnew;
            #pragma unroll
            for (int an = 0; an < 8; an++) {
                o[an][2*h]     *= corr;
                o[an][2*h + 1] *= corr;
            }
        }

        // --- O += P V. V token axis is sigma-permuted, so the accumulator
        // registers ARE the A-fragment: pf = {c0, c2, c1, c3}. No shuffles.
        #pragma unroll
        for (int ko = 0; ko < 8; ko++) {
            uint32_t pf[4];
            pf[0] = tf32b(c[ko][0]);
            pf[1] = tf32b(c[ko][2]);
            pf[2] = tf32b(c[ko][1]);
            pf[3] = tf32b(c[ko][3]);

            uint32_t b[8][2];
            #pragma unroll
            for (int p = 0; p < 4; p++) {
                int row = p * 16 + ((lane >> 4) & 1) * 8 + (lane & 7);
                int col = ko * 8 + ((lane >> 3) & 1) * 4;
                uint32_t t4[4];
                ldsm_x4(t4, smem_u32(&Vts[row * ATSTR + col]));
                b[2*p    ][0] = t4[0]; b[2*p    ][1] = t4[1];
                b[2*p + 1][0] = t4[2]; b[2*p + 1][1] = t4[3];
            }
            #pragma unroll
            for (int an = 0; an < 8; an++) mma_tf32(o[an], pf, b[an]);
        }
    }

    // --- epilogue: normalize, tf32-round, write [B,T,D]
    const int b  = bh >> 4;
    const int hd = bh & 15;
    const int r0 = w * 16 + (lane >> 2);
    #pragma unroll
    for (int h = 0; h < 2; h++) {
        float inv = 1.0f / lst[h];
        int t = qt * 64 + r0 + h * 8;
        float* orow = &g_att[((size_t)b * TSEQ + t) * DMOD + hd * HDIM];
        #pragma unroll
        for (int an = 0; an < 8; an++) {
            int d = an * 8 + t3 * 2;
            float2 v;
            v.x = tf32r(o[an][2*h]     * inv);
            v.y = tf32r(o[an][2*h + 1] * inv);
            *(float2*)&orow[d] = v;
        }
    }
}

__global__ __launch_bounds__(128) void attn_mma() {
    float* Kbuf = dynsm;               // [2][ATILE]
    float* Vbuf = dynsm + 2 * ATILE;   // [2][ATILE]
    const int k = blockIdx.x;          // 0..NCTA_ATT-1
    // Snake schedule over NPASS items ordered by descending qt:
    // item idx -> qt = NQT-1 - idx/32 (cost qt+1), bh = idx%32.
    #pragma unroll
    for (int r = 0; r < (NPASS + NCTA_ATT - 1) / NCTA_ATT; r++) {
        int idx = r * NCTA_ATT + ((r & 1) ? (NCTA_ATT - 1 - k) : k);
        if (idx < NPASS) {
            int qt = (NQT - 1) - (idx >> 5);
            int bh = idx & 31;
            attn_pass(qt, bh, Kbuf, Vbuf);
        }
    }
}

// ---------------------------------------------------------------------------
extern "C" void kernel_launch(void* const* d_in, const int* in_sizes, int n_in,
                              void* d_out, int out_size) {
    (void)in_sizes; (void)n_in; (void)out_size;
    const float* x     = (const float*)d_in[0];
    const float* Wkqv  = (const float*)d_in[1];
    const float* bkqv  = (const float*)d_in[2];
    const float* Wproj = (const float*)d_in[3];
    const float* bproj = (const float*)d_in[4];
    float* out = (float*)d_out;

    cudaFuncSetAttribute(attn_mma, cudaFuncAttributeMaxDynamicSharedMemorySize, ATT_SMEM);

    prep_k<<<4096 + 3072 + 1024, 256>>>(x, Wkqv, Wproj);

    gemm_qkv_mma <<<dim3(3*DMOD/128, MTOK/128), 256>>>(bkqv);
    attn_mma     <<<NCTA_ATT,                   128, ATT_SMEM>>>();
    gemm_proj_mma<<<dim3(DMOD/128,  MTOK/128),  256>>>(bproj, out);
}